// round 8
// baseline (speedup 1.0000x reference)
#include <cuda_runtime.h>
#include <cstdint>

// Fixed shapes per reference: B=256, L=512, N=50000
constexpr int B_SZ   = 256;
constexpr int L_SEQ  = 512;
constexpr int N_LOC  = 50000;
constexpr int HSIZE  = 1024;                 // hash slots (pow2), load factor 0.5
constexpr int NT     = 256;
constexpr int Z_PER_ROW = 7;                 // zeroer CTAs per row
constexpr int ROW_F4 = N_LOC / 4;            // 12,500 float4 per row
constexpr int CHUNK_F4 = (ROW_F4 + Z_PER_ROW - 1) / Z_PER_ROW;  // 1786
constexpr int N_ZERO = B_SZ * Z_PER_ROW;     // 1792
constexpr int PAD    = 32;                   // 128B padding between row counters

__device__ int g_done[B_SZ * PAD];           // zero-initialized at module load

__global__ __launch_bounds__(NT, 8)
void fused_kernel(const int* __restrict__ loc_seq,
                  const int* __restrict__ mask,
                  const float* __restrict__ rw_p,
                  const float* __restrict__ fw_p,
                  float* __restrict__ out)
{
    const int bid = blockIdx.x;
    const int tid = threadIdx.x;

    if (bid >= B_SZ) {
        // ====================== zeroer path ======================
        const int zi = bid - B_SZ;           // 0..1791
        const int b  = zi / Z_PER_ROW;
        const int q  = zi % Z_PER_ROW;

        float4* row4 = reinterpret_cast<float4*>(out + (size_t)b * N_LOC);
        const float4 z = make_float4(0.f, 0.f, 0.f, 0.f);
        const int i0 = q * CHUNK_F4;
        const int i1 = min(i0 + CHUNK_F4, ROW_F4);
        #pragma unroll 4
        for (int i = i0 + tid; i < i1; i += NT)
            row4[i] = z;

        __threadfence();                     // order my stores device-wide
        __syncthreads();                     // all threads' stores issued+fenced
        if (tid == 0)
            atomicAdd(&g_done[b * PAD], 1);  // signal chunk complete
        return;
    }

    // ====================== builder path (one CTA per row) ======================
    const int b = bid;

    __shared__ int      h_key[HSIZE];
    __shared__ int      h_cnt[HSIZE];
    __shared__ unsigned h_rec[HSIZE];        // float bits; all values >= 0
    __shared__ int      s_maxcnt;

    #pragma unroll 4
    for (int i = tid; i < HSIZE; i += NT) {
        h_key[i] = -1;
        h_cnt[i] = 0;
        h_rec[i] = 0u;
    }
    if (tid == 0) s_maxcnt = 0;
    __syncthreads();

    const float l2rw = log2f(*rw_p);

    const int2* lrow = reinterpret_cast<const int2*>(loc_seq + (size_t)b * L_SEQ);
    const int2* mrow = reinterpret_cast<const int2*>(mask    + (size_t)b * L_SEQ);
    const int2 lk = lrow[tid];
    const int2 mk = mrow[tid];

    #pragma unroll
    for (int j = 0; j < 2; j++) {
        const int t   = 2 * tid + j;
        const int key = (j == 0) ? lk.x : lk.y;
        const int m   = (j == 0) ? mk.x : mk.y;
        const float rec = m ? exp2f((float)(L_SEQ - 1 - t) * l2rw) : 0.0f;

        unsigned h = ((unsigned)key * 2654435761u) & (HSIZE - 1);
        for (;;) {
            int cur = h_key[h];
            if (cur == key) break;
            if (cur == -1) {
                int prev = atomicCAS(&h_key[h], -1, key);
                if (prev == -1 || prev == key) break;
            }
            h = (h + 1) & (HSIZE - 1);
        }
        atomicAdd(&h_cnt[h], m);
        atomicMax(&h_rec[h], __float_as_uint(rec));
    }
    __syncthreads();

    // block reduce: max frequency count (4 slots per thread)
    int mf = 0;
    #pragma unroll 4
    for (int i = tid; i < HSIZE; i += NT) mf = max(mf, h_cnt[i]);
    #pragma unroll
    for (int o = 16; o > 0; o >>= 1) mf = max(mf, __shfl_xor_sync(0xFFFFFFFFu, mf, o));
    if ((tid & 31) == 0) atomicMax(&s_maxcnt, mf);

    // wait for this row's 7 zeroers (flags validated replay-safe in R5)
    if (tid == 0) {
        volatile int* dp = &g_done[b * PAD];
        while (*dp != Z_PER_ROW) __nanosleep(64);
        __threadfence();                     // acquire: zero stores visible
        *dp = 0;                             // reset for next graph replay (sole consumer)
    }
    __syncthreads();

    const float inv = (*fw_p) / fmaxf((float)s_maxcnt, 1.0f);

    // scatter final values directly from the smem hash
    float* row = out + (size_t)b * N_LOC;
    #pragma unroll 4
    for (int i = tid; i < HSIZE; i += NT) {
        const int key = h_key[i];
        if (key >= 0) {
            row[key] = __uint_as_float(h_rec[i]) + (float)h_cnt[i] * inv;
        }
    }
}

extern "C" void kernel_launch(void* const* d_in, const int* in_sizes, int n_in,
                              void* d_out, int out_size)
{
    const int*   loc_seq = (const int*)  d_in[0];   // (B, L) int32
    const int*   mask    = (const int*)  d_in[1];   // (B, L) int32
    const float* rw      = (const float*)d_in[2];   // scalar
    const float* fw      = (const float*)d_in[3];   // scalar
    float*       out     = (float*)d_out;           // (B, N) float32

    fused_kernel<<<B_SZ + N_ZERO, NT>>>(loc_seq, mask, rw, fw, out);
}